// round 7
// baseline (speedup 1.0000x reference)
#include <cuda_runtime.h>
#include <cstdint>

// Problem constants (fixed by the reference)
#define NSLOT 1048576u      // N
#define WDIM  64            // W
#define EPSF  1e-8f

#define HIST_BUCKETS 2048   // u in [0,1) -> bucket = float_bits(u)>>19 in [0, 2032]
#define HIST_SHIFT   19
#define SORT_CAP     8192   // max gathered candidates
#define KSEL         64     // minimum number of smallest elements to gather

#define COS_BLOCKS   (NSLOT / 256)        // 4096
#define ELEM_BLOCKS  (NSLOT / 1024)       // 1024, 4 rows per thread
#define P2_BLOCKS    (NSLOT / 1024)       // 1024, 4 floats per thread

// ---------------- scratch (device globals; no allocations allowed) ------------
__device__ float              g_partial_sum[COS_BLOCKS];
__device__ unsigned           g_hist[HIST_BUCKETS];
__device__ float              g_inv_sum;
__device__ unsigned           g_thresh;   // gathered iff float_bits(usage) < g_thresh
__device__ unsigned           g_count;
__device__ unsigned long long g_pairs[SORT_CAP];
__device__ float              g_scale2;   // beta * log2(e) / max(||key||, eps)
__device__ float              g_beta2;    // beta * log2(e)   (softmax shift)

// ---------------- helpers ------------------------------------------------------
__device__ __forceinline__ float warp_sum(float v) {
    #pragma unroll
    for (int o = 16; o; o >>= 1) v += __shfl_xor_sync(0xffffffffu, v, o);
    return v;
}
__device__ __forceinline__ float rsqrt_approx(float x) {
    float r; asm("rsqrt.approx.f32 %0, %1;" : "=f"(r) : "f"(x)); return r;
}
__device__ __forceinline__ float ex2_approx(float x) {
    float r; asm("ex2.approx.f32 %0, %1;" : "=f"(r) : "f"(x)); return r;
}

// ---------------- kernels ------------------------------------------------------

// (1) 1 block, 256 threads: zero hist/count, compute key scale/shift (log2 domain).
__global__ void k_prep(const float* __restrict__ key, const float* __restrict__ beta) {
    const int t = threadIdx.x;
    #pragma unroll
    for (int i = 0; i < HIST_BUCKETS / 256; i++) g_hist[t + i * 256] = 0u;
    if (t == 0) g_count = 0u;
    if (t < 32) {
        float a = key[t], b = key[t + 32];
        float s = warp_sum(a * a + b * b);
        if (t == 0) {
            float kn = fmaxf(sqrtf(s), EPSF);
            float bv = beta[0];
            g_scale2 = bv * 1.44269504088896f / kn;
            g_beta2  = bv * 1.44269504088896f;
        }
    }
}

// (2) Elementwise pass: retention, usage, allocation-zero, histogram. 4 rows/thread.
__global__ void __launch_bounds__(256) k_elem(
    const float* __restrict__ fg, const float* __restrict__ rw,
    const float* __restrict__ pu, const float* __restrict__ ww,
    float* __restrict__ out)
{
    const unsigned q = blockIdx.x * 256u + threadIdx.x;     // float4 row-group index
    const float4 f = *reinterpret_cast<const float4*>(fg);
    const float4* rw4 = reinterpret_cast<const float4*>(rw);
    float4 r0 = rw4[4 * q], r1 = rw4[4 * q + 1], r2 = rw4[4 * q + 2], r3 = rw4[4 * q + 3];
    float4 p = reinterpret_cast<const float4*>(pu)[q];
    float4 w = reinterpret_cast<const float4*>(ww)[q];

    float4 ret;
    ret.x = (1.f - r0.x * f.x) * (1.f - r0.y * f.y) * (1.f - r0.z * f.z) * (1.f - r0.w * f.w);
    ret.y = (1.f - r1.x * f.x) * (1.f - r1.y * f.y) * (1.f - r1.z * f.z) * (1.f - r1.w * f.w);
    ret.z = (1.f - r2.x * f.x) * (1.f - r2.y * f.y) * (1.f - r2.z * f.z) * (1.f - r2.w * f.w);
    ret.w = (1.f - r3.x * f.x) * (1.f - r3.y * f.y) * (1.f - r3.z * f.z) * (1.f - r3.w * f.w);

    float4 u;
    u.x = (p.x + w.x - p.x * w.x) * ret.x;
    u.y = (p.y + w.y - p.y * w.y) * ret.y;
    u.z = (p.z + w.z - p.z * w.z) * ret.z;
    u.w = (p.w + w.w - p.w * w.w) * ret.w;

    reinterpret_cast<float4*>(out + NSLOT)[q]      = ret;
    reinterpret_cast<float4*>(out + 2u * NSLOT)[q] = u;
    reinterpret_cast<float4*>(out + 3u * NSLOT)[q] = make_float4(0.f, 0.f, 0.f, 0.f);

    const int lane = threadIdx.x & 31;
    #pragma unroll
    for (int c = 0; c < 4; c++) {
        float uv = (c == 0) ? u.x : (c == 1) ? u.y : (c == 2) ? u.z : u.w;
        unsigned b = __float_as_uint(uv) >> HIST_SHIFT;
        if (b >= HIST_BUCKETS) b = HIST_BUCKETS - 1;
        unsigned peers = __match_any_sync(0xffffffffu, b);
        if (lane == __ffs(peers) - 1) atomicAdd(&g_hist[b], (unsigned)__popc(peers));
    }
}

// (3) 1 warp: histogram -> threshold (first bucket covering >= KSEL, cap SORT_CAP).
__global__ void k_midh() {
    const int lane = threadIdx.x;                 // 32 threads
    unsigned loc[64]; unsigned s = 0;
    #pragma unroll
    for (int i = 0; i < 64; i++) { loc[i] = g_hist[lane * 64 + i]; s += loc[i]; }
    // exclusive scan of per-lane sums
    unsigned excl = s;
    #pragma unroll
    for (int o = 1; o < 32; o <<= 1) {
        unsigned v = __shfl_up_sync(0xffffffffu, excl, o);
        if (lane >= o) excl += v;
    }
    excl -= s;
    int t1 = 0x7fffffff, t2 = 0x7fffffff;
    unsigned cum = excl;
    #pragma unroll
    for (int i = 0; i < 64; i++) {
        cum += loc[i];
        int b = lane * 64 + i;
        if (cum >= KSEL    && t1 == 0x7fffffff) t1 = b;
        if (cum > SORT_CAP && t2 == 0x7fffffff) t2 = b;
    }
    #pragma unroll
    for (int o = 16; o; o >>= 1) {
        t1 = min(t1, __shfl_xor_sync(0xffffffffu, t1, o));
        t2 = min(t2, __shfl_xor_sync(0xffffffffu, t2, o));
    }
    if (lane == 0) {
        int T = (t1 == 0x7fffffff) ? HIST_BUCKETS - 1 : t1;
        if (t2 != 0x7fffffff && t2 - 1 < T) T = t2 - 1;
        if (T < 0) T = 0;
        g_thresh = ((unsigned)(T + 1)) << HIST_SHIFT;
    }
}

// (4) Cosine pass. 8-lane group per row, float2 loads: each LDG.64 covers
// 4 rows x 64B at 256B stride = 4 lines, zero sector overfetch, minimal L1
// wavefronts. 6 shfl_xor per 4 rows + 2 ownership shfl = 2 SHFL/row.
//   out[0..N) = exp(sim*beta - beta)   + per-block sums of e.
__global__ void __launch_bounds__(256) k_cos(
    const float* __restrict__ mem, const float* __restrict__ key,
    float* __restrict__ out)
{
    __shared__ float ssum[8];
    const int t = threadIdx.x, lane = t & 31, warp = t >> 5;
    const int group = lane >> 3, gl = lane & 7;

    const float2* key2 = reinterpret_cast<const float2*>(key);
    const float2 kc0 = key2[gl], kc1 = key2[gl + 8], kc2 = key2[gl + 16], kc3 = key2[gl + 24];

    const unsigned rowbase = blockIdx.x * 256u + (unsigned)(warp * 32);
    const float2* g = reinterpret_cast<const float2*>(mem) + (size_t)rowbase * 32;

    float my_d = 0.0f, my_n = 0.0f;
    #pragma unroll
    for (int j = 0; j < 8; j++) {
        const float2* rp = g + (size_t)(4 * j + group) * 32;
        float2 a = rp[gl], b = rp[gl + 8], c = rp[gl + 16], e2 = rp[gl + 24];
        float d = a.x * kc0.x + a.y * kc0.y + b.x * kc1.x + b.y * kc1.y
                + c.x * kc2.x + c.y * kc2.y + e2.x * kc3.x + e2.y * kc3.y;
        float n = a.x * a.x + a.y * a.y + b.x * b.x + b.y * b.y
                + c.x * c.x + c.y * c.y + e2.x * e2.x + e2.y * e2.y;
        #pragma unroll
        for (int o = 4; o; o >>= 1) {           // butterfly within 8-lane groups
            d += __shfl_xor_sync(0xffffffffu, d, o);
            n += __shfl_xor_sync(0xffffffffu, n, o);
        }
        float od = __shfl_sync(0xffffffffu, d, (lane & 3) * 8);
        float on = __shfl_sync(0xffffffffu, n, (lane & 3) * 8);
        if ((lane >> 2) == j) { my_d = od; my_n = on; }
    }

    const unsigned i = blockIdx.x * 256u + (unsigned)t;
    float rs = rsqrt_approx(fmaxf(my_n, 1e-16f));           // 1/max(||row||,1e-8)
    float e  = ex2_approx(my_d * rs * g_scale2 - g_beta2);  // exp(sim*b - b) in (0,1]
    out[i] = e;

    float s = warp_sum(e);
    if (lane == 0) ssum[warp] = s;
    __syncthreads();
    if (t == 0) {
        float tot = ssum[0];
        #pragma unroll
        for (int j = 1; j < 8; j++) tot += ssum[j];
        g_partial_sum[blockIdx.x] = tot;
    }
}

// (5) 1 block, 1024 threads: reduce partial sums -> 1/sum.
__global__ void k_mids() {
    const int t = threadIdx.x;
    __shared__ float sm[32];
    float s = 0.0f;
    #pragma unroll
    for (int j = 0; j < COS_BLOCKS / 1024; j++) s += g_partial_sum[t + j * 1024];
    s = warp_sum(s);
    int lane = t & 31, warp = t >> 5;
    if (lane == 0) sm[warp] = s;
    __syncthreads();
    if (t < 32) {
        float v = sm[t];
        v = warp_sum(v);
        if (t == 0) g_inv_sum = 1.0f / v;
    }
}

// (6) Normalize content weighting + gather smallest usages (float4 per thread).
__global__ void __launch_bounds__(256) k_pass2(float* __restrict__ out) {
    const unsigned q = blockIdx.x * 256u + threadIdx.x;     // float4 index
    float4* o4 = reinterpret_cast<float4*>(out);
    float4 e = o4[q];
    float4 u = o4[(2u * NSLOT) / 4 + q];
    const float inv = g_inv_sum;
    e.x *= inv; e.y *= inv; e.z *= inv; e.w *= inv;
    o4[q] = e;

    const unsigned th = g_thresh;
    const unsigned base = q * 4u;
    #pragma unroll
    for (int c = 0; c < 4; c++) {
        float uv = (c == 0) ? u.x : (c == 1) ? u.y : (c == 2) ? u.z : u.w;
        if (__float_as_uint(uv) < th) {
            unsigned pos = atomicAdd(&g_count, 1u);
            if (pos < SORT_CAP)
                g_pairs[pos] = ((unsigned long long)__float_as_uint(uv) << 32)
                             | (unsigned long long)(base + c);
        }
    }
}

// (7) Single block: bitonic sort gathered (usage_bits:index) pairs (stable order
// of jnp argsort), then serial cumprod with early exit at prod==0.
__global__ void k_sortalloc(float* __restrict__ out) {
    extern __shared__ unsigned long long sp[];
    const unsigned count = min(g_count, (unsigned)SORT_CAP);
    unsigned n = 2;
    while (n < count) n <<= 1;

    const int t = threadIdx.x;
    for (unsigned i = t; i < n; i += 1024)
        sp[i] = (i < count) ? g_pairs[i] : 0xFFFFFFFFFFFFFFFFull;
    __syncthreads();

    for (unsigned k = 2; k <= n; k <<= 1) {
        for (unsigned j = k >> 1; j > 0; j >>= 1) {
            for (unsigned i = t; i < n; i += 1024) {
                unsigned ixj = i ^ j;
                if (ixj > i) {
                    bool up = ((i & k) == 0);
                    unsigned long long a = sp[i], b = sp[ixj];
                    if ((a > b) == up) { sp[i] = b; sp[ixj] = a; }
                }
            }
            __syncthreads();
        }
    }

    if (t == 0) {
        float prod = 1.0f, prev = 0.0f;
        for (unsigned j = 0; j < count; j++) {
            unsigned long long p = sp[j];
            float    sv  = __uint_as_float((unsigned)(p >> 32));
            unsigned idx = (unsigned)(p & 0xFFFFFFFFull);
            float a = (j == 0) ? (1.0f - sv) : (1.0f - prev) * prod;
            out[3u * NSLOT + idx] = a;
            prod *= sv;
            prev  = sv;
            if (prod == 0.0f) break;   // remaining allocations are exactly 0
        }
    }
}

// ---------------- launch --------------------------------------------------------
extern "C" void kernel_launch(void* const* d_in, const int* in_sizes, int n_in,
                              void* d_out, int out_size)
{
    const float* key  = (const float*)d_in[0];  // desired_content (64)
    const float* mem  = (const float*)d_in[1];  // memory (N*W)
    const float* beta = (const float*)d_in[2];  // key_strength (1)
    const float* fg   = (const float*)d_in[3];  // free_gate (4)
    const float* rw   = (const float*)d_in[4];  // read_weighting (N*4)
    const float* pu   = (const float*)d_in[5];  // previous_usage (N)
    const float* ww   = (const float*)d_in[6];  // write_weighting (N)
    float* out = (float*)d_out;                 // (4, N) float32

    cudaFuncSetAttribute(k_sortalloc, cudaFuncAttributeMaxDynamicSharedMemorySize,
                         SORT_CAP * (int)sizeof(unsigned long long));

    // NOTE: ncu profiles the 4th launch -> k_cos is deliberately 4th.
    k_prep      <<<1, 256>>>(key, beta);
    k_elem      <<<ELEM_BLOCKS, 256>>>(fg, rw, pu, ww, out);
    k_midh      <<<1, 32>>>();
    k_cos       <<<COS_BLOCKS, 256>>>(mem, key, out);
    k_mids      <<<1, 1024>>>();
    k_pass2     <<<P2_BLOCKS, 256>>>(out);
    k_sortalloc <<<1, 1024, SORT_CAP * (int)sizeof(unsigned long long)>>>(out);
}

// round 8
// speedup vs baseline: 2.3374x; 2.3374x over previous
#include <cuda_runtime.h>
#include <cstdint>

// Problem constants (fixed by the reference)
#define NSLOT 1048576u      // N
#define WDIM  64            // W
#define EPSF  1e-8f

#define HIST_BUCKETS 2048   // u in [0,1) -> bucket = float_bits(u)>>19 in [0, 2032]
#define HIST_SHIFT   19
#define SORT_CAP     8192   // max gathered candidates
#define KSEL         64     // minimum number of smallest elements to gather

#define COS_BLOCKS   (NSLOT / 256)        // 4096
#define ELEM_BLOCKS  (NSLOT / 1024)       // 1024, 4 rows per thread
#define P2_BLOCKS    (NSLOT / 1024)       // 1024, 4 floats per thread

// ---------------- scratch (device globals; no allocations allowed) ------------
__device__ float              g_partial_sum[COS_BLOCKS];
__device__ unsigned           g_hist[HIST_BUCKETS];
__device__ float              g_inv_sum;
__device__ unsigned           g_thresh;   // gathered iff float_bits(usage) < g_thresh
__device__ unsigned           g_count;
__device__ unsigned long long g_pairs[SORT_CAP];
__device__ float              g_scale2;   // beta * log2(e) / max(||key||, eps)
__device__ float              g_beta2;    // beta * log2(e)   (softmax shift)

// ---------------- helpers ------------------------------------------------------
__device__ __forceinline__ float warp_sum(float v) {
    #pragma unroll
    for (int o = 16; o; o >>= 1) v += __shfl_xor_sync(0xffffffffu, v, o);
    return v;
}
__device__ __forceinline__ float rsqrt_approx(float x) {
    float r; asm("rsqrt.approx.f32 %0, %1;" : "=f"(r) : "f"(x)); return r;
}
__device__ __forceinline__ float ex2_approx(float x) {
    float r; asm("ex2.approx.f32 %0, %1;" : "=f"(r) : "f"(x)); return r;
}

// ---------------- kernels ------------------------------------------------------

// (1) 1 block, 256 threads: zero hist/count, compute key scale/shift (log2 domain).
__global__ void k_prep(const float* __restrict__ key, const float* __restrict__ beta) {
    const int t = threadIdx.x;
    #pragma unroll
    for (int i = 0; i < HIST_BUCKETS / 256; i++) g_hist[t + i * 256] = 0u;
    if (t == 0) g_count = 0u;
    if (t < 32) {
        float a = key[t], b = key[t + 32];
        float s = warp_sum(a * a + b * b);
        if (t == 0) {
            float kn = fmaxf(sqrtf(s), EPSF);
            float bv = beta[0];
            g_scale2 = bv * 1.44269504088896f / kn;
            g_beta2  = bv * 1.44269504088896f;
        }
    }
}

// (2) Cosine pass. 8-lane group per row, float2 loads (4 lines per LDG.64,
// zero overfetch). 2 SHFL/row.   out[0..N) = exp(sim*b - b) + block sums.
__global__ void __launch_bounds__(256) k_cos(
    const float* __restrict__ mem, const float* __restrict__ key,
    float* __restrict__ out)
{
    __shared__ float ssum[8];
    const int t = threadIdx.x, lane = t & 31, warp = t >> 5;
    const int group = lane >> 3, gl = lane & 7;

    const float2* key2 = reinterpret_cast<const float2*>(key);
    const float2 kc0 = key2[gl], kc1 = key2[gl + 8], kc2 = key2[gl + 16], kc3 = key2[gl + 24];

    const unsigned rowbase = blockIdx.x * 256u + (unsigned)(warp * 32);
    const float2* g = reinterpret_cast<const float2*>(mem) + (size_t)rowbase * 32;

    float my_d = 0.0f, my_n = 0.0f;
    #pragma unroll
    for (int j = 0; j < 8; j++) {
        const float2* rp = g + (size_t)(4 * j + group) * 32;
        float2 a = rp[gl], b = rp[gl + 8], c = rp[gl + 16], e2 = rp[gl + 24];
        float d = a.x * kc0.x + a.y * kc0.y + b.x * kc1.x + b.y * kc1.y
                + c.x * kc2.x + c.y * kc2.y + e2.x * kc3.x + e2.y * kc3.y;
        float n = a.x * a.x + a.y * a.y + b.x * b.x + b.y * b.y
                + c.x * c.x + c.y * c.y + e2.x * e2.x + e2.y * e2.y;
        #pragma unroll
        for (int o = 4; o; o >>= 1) {           // butterfly within 8-lane groups
            d += __shfl_xor_sync(0xffffffffu, d, o);
            n += __shfl_xor_sync(0xffffffffu, n, o);
        }
        float od = __shfl_sync(0xffffffffu, d, (lane & 3) * 8);
        float on = __shfl_sync(0xffffffffu, n, (lane & 3) * 8);
        if ((lane >> 2) == j) { my_d = od; my_n = on; }
    }

    const unsigned i = blockIdx.x * 256u + (unsigned)t;
    float rs = rsqrt_approx(fmaxf(my_n, 1e-16f));           // 1/max(||row||,1e-8)
    float e  = ex2_approx(my_d * rs * g_scale2 - g_beta2);  // exp(sim*b - b) in (0,1]
    out[i] = e;

    float s = warp_sum(e);
    if (lane == 0) ssum[warp] = s;
    __syncthreads();
    if (t == 0) {
        float tot = ssum[0];
        #pragma unroll
        for (int j = 1; j < 8; j++) tot += ssum[j];
        g_partial_sum[blockIdx.x] = tot;
    }
}

// (3) 1 block, 1024 threads: reduce partial sums -> 1/sum.
__global__ void k_mids() {
    const int t = threadIdx.x;
    __shared__ float sm[32];
    float s = 0.0f;
    #pragma unroll
    for (int j = 0; j < COS_BLOCKS / 1024; j++) s += g_partial_sum[t + j * 1024];
    s = warp_sum(s);
    int lane = t & 31, warp = t >> 5;
    if (lane == 0) sm[warp] = s;
    __syncthreads();
    if (t < 32) {
        float v = sm[t];
        v = warp_sum(v);
        if (t == 0) g_inv_sum = 1.0f / v;
    }
}

// (4) Elementwise pass: retention, usage, allocation-zero, histogram with
// SHARED-MEMORY privatization (global L2 atomic contention was the R7 binder).
// Flush only non-zero buckets (~150/block).
__global__ void __launch_bounds__(256) k_elem(
    const float* __restrict__ fg, const float* __restrict__ rw,
    const float* __restrict__ pu, const float* __restrict__ ww,
    float* __restrict__ out)
{
    __shared__ unsigned shist[HIST_BUCKETS];
    const int t = threadIdx.x;
    #pragma unroll
    for (int i = 0; i < HIST_BUCKETS / 256; i++) shist[t + i * 256] = 0u;
    __syncthreads();

    const unsigned q = blockIdx.x * 256u + (unsigned)t;     // float4 row-group index
    const float4 f = *reinterpret_cast<const float4*>(fg);
    const float4* rw4 = reinterpret_cast<const float4*>(rw);
    float4 r0 = rw4[4 * q], r1 = rw4[4 * q + 1], r2 = rw4[4 * q + 2], r3 = rw4[4 * q + 3];
    float4 p = reinterpret_cast<const float4*>(pu)[q];
    float4 w = reinterpret_cast<const float4*>(ww)[q];

    float4 ret;
    ret.x = (1.f - r0.x * f.x) * (1.f - r0.y * f.y) * (1.f - r0.z * f.z) * (1.f - r0.w * f.w);
    ret.y = (1.f - r1.x * f.x) * (1.f - r1.y * f.y) * (1.f - r1.z * f.z) * (1.f - r1.w * f.w);
    ret.z = (1.f - r2.x * f.x) * (1.f - r2.y * f.y) * (1.f - r2.z * f.z) * (1.f - r2.w * f.w);
    ret.w = (1.f - r3.x * f.x) * (1.f - r3.y * f.y) * (1.f - r3.z * f.z) * (1.f - r3.w * f.w);

    float4 u;
    u.x = (p.x + w.x - p.x * w.x) * ret.x;
    u.y = (p.y + w.y - p.y * w.y) * ret.y;
    u.z = (p.z + w.z - p.z * w.z) * ret.z;
    u.w = (p.w + w.w - p.w * w.w) * ret.w;

    reinterpret_cast<float4*>(out + NSLOT)[q]      = ret;
    reinterpret_cast<float4*>(out + 2u * NSLOT)[q] = u;
    reinterpret_cast<float4*>(out + 3u * NSLOT)[q] = make_float4(0.f, 0.f, 0.f, 0.f);

    #pragma unroll
    for (int c = 0; c < 4; c++) {
        float uv = (c == 0) ? u.x : (c == 1) ? u.y : (c == 2) ? u.z : u.w;
        unsigned b = __float_as_uint(uv) >> HIST_SHIFT;
        if (b >= HIST_BUCKETS) b = HIST_BUCKETS - 1;
        atomicAdd(&shist[b], 1u);                 // smem atomic: no L2 contention
    }
    __syncthreads();

    #pragma unroll
    for (int i = 0; i < HIST_BUCKETS / 256; i++) {
        unsigned v = shist[t + i * 256];
        if (v) atomicAdd(&g_hist[t + i * 256], v);
    }
}

// (5) 1 warp: histogram -> threshold (first bucket covering >= KSEL, cap SORT_CAP).
__global__ void k_midh() {
    const int lane = threadIdx.x;                 // 32 threads
    unsigned loc[64]; unsigned s = 0;
    #pragma unroll
    for (int i = 0; i < 64; i++) { loc[i] = g_hist[lane * 64 + i]; s += loc[i]; }
    unsigned excl = s;
    #pragma unroll
    for (int o = 1; o < 32; o <<= 1) {
        unsigned v = __shfl_up_sync(0xffffffffu, excl, o);
        if (lane >= o) excl += v;
    }
    excl -= s;
    int t1 = 0x7fffffff, t2 = 0x7fffffff;
    unsigned cum = excl;
    #pragma unroll
    for (int i = 0; i < 64; i++) {
        cum += loc[i];
        int b = lane * 64 + i;
        if (cum >= KSEL    && t1 == 0x7fffffff) t1 = b;
        if (cum > SORT_CAP && t2 == 0x7fffffff) t2 = b;
    }
    #pragma unroll
    for (int o = 16; o; o >>= 1) {
        t1 = min(t1, __shfl_xor_sync(0xffffffffu, t1, o));
        t2 = min(t2, __shfl_xor_sync(0xffffffffu, t2, o));
    }
    if (lane == 0) {
        int T = (t1 == 0x7fffffff) ? HIST_BUCKETS - 1 : t1;
        if (t2 != 0x7fffffff && t2 - 1 < T) T = t2 - 1;
        if (T < 0) T = 0;
        g_thresh = ((unsigned)(T + 1)) << HIST_SHIFT;
    }
}

// (6) Normalize content weighting + gather smallest usages (float4 per thread).
__global__ void __launch_bounds__(256) k_pass2(float* __restrict__ out) {
    const unsigned q = blockIdx.x * 256u + threadIdx.x;     // float4 index
    float4* o4 = reinterpret_cast<float4*>(out);
    float4 e = o4[q];
    float4 u = o4[(2u * NSLOT) / 4 + q];
    const float inv = g_inv_sum;
    e.x *= inv; e.y *= inv; e.z *= inv; e.w *= inv;
    o4[q] = e;

    const unsigned th = g_thresh;
    const unsigned base = q * 4u;
    #pragma unroll
    for (int c = 0; c < 4; c++) {
        float uv = (c == 0) ? u.x : (c == 1) ? u.y : (c == 2) ? u.z : u.w;
        if (__float_as_uint(uv) < th) {
            unsigned pos = atomicAdd(&g_count, 1u);
            if (pos < SORT_CAP)
                g_pairs[pos] = ((unsigned long long)__float_as_uint(uv) << 32)
                             | (unsigned long long)(base + c);
        }
    }
}

// (7) Single block: bitonic sort gathered (usage_bits:index) pairs (stable order
// of jnp argsort), then serial cumprod with early exit at prod==0.
__global__ void k_sortalloc(float* __restrict__ out) {
    extern __shared__ unsigned long long sp[];
    const unsigned count = min(g_count, (unsigned)SORT_CAP);
    unsigned n = 2;
    while (n < count) n <<= 1;

    const int t = threadIdx.x;
    for (unsigned i = t; i < n; i += 1024)
        sp[i] = (i < count) ? g_pairs[i] : 0xFFFFFFFFFFFFFFFFull;
    __syncthreads();

    for (unsigned k = 2; k <= n; k <<= 1) {
        for (unsigned j = k >> 1; j > 0; j >>= 1) {
            for (unsigned i = t; i < n; i += 1024) {
                unsigned ixj = i ^ j;
                if (ixj > i) {
                    bool up = ((i & k) == 0);
                    unsigned long long a = sp[i], b = sp[ixj];
                    if ((a > b) == up) { sp[i] = b; sp[ixj] = a; }
                }
            }
            __syncthreads();
        }
    }

    if (t == 0) {
        float prod = 1.0f, prev = 0.0f;
        for (unsigned j = 0; j < count; j++) {
            unsigned long long p = sp[j];
            float    sv  = __uint_as_float((unsigned)(p >> 32));
            unsigned idx = (unsigned)(p & 0xFFFFFFFFull);
            float a = (j == 0) ? (1.0f - sv) : (1.0f - prev) * prod;
            out[3u * NSLOT + idx] = a;
            prod *= sv;
            prev  = sv;
            if (prod == 0.0f) break;   // remaining allocations are exactly 0
        }
    }
}

// ---------------- launch --------------------------------------------------------
extern "C" void kernel_launch(void* const* d_in, const int* in_sizes, int n_in,
                              void* d_out, int out_size)
{
    const float* key  = (const float*)d_in[0];  // desired_content (64)
    const float* mem  = (const float*)d_in[1];  // memory (N*W)
    const float* beta = (const float*)d_in[2];  // key_strength (1)
    const float* fg   = (const float*)d_in[3];  // free_gate (4)
    const float* rw   = (const float*)d_in[4];  // read_weighting (N*4)
    const float* pu   = (const float*)d_in[5];  // previous_usage (N)
    const float* ww   = (const float*)d_in[6];  // write_weighting (N)
    float* out = (float*)d_out;                 // (4, N) float32

    cudaFuncSetAttribute(k_sortalloc, cudaFuncAttributeMaxDynamicSharedMemorySize,
                         SORT_CAP * (int)sizeof(unsigned long long));

    // NOTE: ncu profiles the 4th launch -> k_elem is deliberately 4th this round.
    k_prep      <<<1, 256>>>(key, beta);
    k_cos       <<<COS_BLOCKS, 256>>>(mem, key, out);
    k_mids      <<<1, 1024>>>();
    k_elem      <<<ELEM_BLOCKS, 256>>>(fg, rw, pu, ww, out);
    k_midh      <<<1, 32>>>();
    k_pass2     <<<P2_BLOCKS, 256>>>(out);
    k_sortalloc <<<1, 1024, SORT_CAP * (int)sizeof(unsigned long long)>>>(out);
}